// round 2
// baseline (speedup 1.0000x reference)
#include <cuda_runtime.h>

// Problem constants
constexpr int B  = 4;
constexpr int T  = 1024;
constexpr int E  = 1024;
constexpr int H  = 16;
constexpr int DH = 64;
constexpr int M  = B * T;        // 4096 rows of x
constexpr int HD = H * DH;       // 1024

// Scratch (static device globals: allowed; no runtime allocation)
__device__ float g_Q[B * H * T * DH];   // [b][h][t][d]
__device__ float g_K[B * H * T * DH];
__device__ float g_V[B * H * T * DH];
__device__ float g_O[M * HD];           // [b*T + t][h*DH + d]

// ---------------------------------------------------------------------------
// Kernel 1: fused QKV projection.
// C[M, 3072] = x[M, E] * Wcat, where column n selects Wq/Wk/Wv and (h, d).
// 128x128 tile, BK=8, 256 threads, 8x8 per-thread micro-tile.
// Epilogue writes straight into g_Q/g_K/g_V in [b][h][t][d] layout.
// ---------------------------------------------------------------------------
__global__ void __launch_bounds__(256, 2)
qkv_kernel(const float* __restrict__ x,
           const float* __restrict__ Wq,
           const float* __restrict__ Wk,
           const float* __restrict__ Wv)
{
    __shared__ float As[8][128];
    __shared__ float Bs[8][128];

    const int m0   = blockIdx.x * 128;
    const int nblk = blockIdx.y;          // 0..23
    const int sel  = nblk >> 3;           // 0: Q, 1: K, 2: V (8 tiles each)
    const int nn0  = (nblk & 7) * 128;    // column offset within the projection

    const float* Wsel = (sel == 0) ? Wq : (sel == 1) ? Wk : Wv;
    float*       Out  = (sel == 0) ? g_Q : (sel == 1) ? g_K : g_V;

    const int tid = threadIdx.x;
    const int tx  = tid & 15;
    const int ty  = tid >> 4;

    // A tile load mapping: each thread loads one float4 per k-step
    const int rowA = tid >> 1;
    const int colA = (tid & 1) * 4;
    // B tile load mapping: each thread loads 4 scalars (gathered, stride DH)
    const int kB = tid >> 5;
    const int nB = (tid & 31) * 4;

    float acc[8][8] = {};

    const float* Aptr = x + (m0 + rowA) * E + colA;

    for (int k0 = 0; k0 < E; k0 += 8) {
        float4 av = *(const float4*)(Aptr + k0);
        As[colA + 0][rowA] = av.x;
        As[colA + 1][rowA] = av.y;
        As[colA + 2][rowA] = av.z;
        As[colA + 3][rowA] = av.w;

        #pragma unroll
        for (int q = 0; q < 4; q++) {
            int n = nn0 + nB + q;                       // nB+q never crosses a head
            Bs[kB][nB + q] = Wsel[((n >> 6) * E + (k0 + kB)) * DH + (n & 63)];
        }
        __syncthreads();

        #pragma unroll
        for (int k = 0; k < 8; k++) {
            float4 a0 = *(const float4*)&As[k][ty * 8];
            float4 a1 = *(const float4*)&As[k][ty * 8 + 4];
            float4 b0 = *(const float4*)&Bs[k][tx * 8];
            float4 b1 = *(const float4*)&Bs[k][tx * 8 + 4];
            float a[8] = {a0.x, a0.y, a0.z, a0.w, a1.x, a1.y, a1.z, a1.w};
            float b[8] = {b0.x, b0.y, b0.z, b0.w, b1.x, b1.y, b1.z, b1.w};
            #pragma unroll
            for (int i = 0; i < 8; i++)
                #pragma unroll
                for (int j = 0; j < 8; j++)
                    acc[i][j] += a[i] * b[j];
        }
        __syncthreads();
    }

    // Epilogue: (m, n) -> g_{Q,K,V}[b][h][t][d]; 8 consecutive n stay in one head
    const int n  = nn0 + tx * 8;
    const int h  = n >> 6;
    const int d  = n & 63;
    #pragma unroll
    for (int i = 0; i < 8; i++) {
        int m  = m0 + ty * 8 + i;
        int bb = m >> 10;
        int t  = m & 1023;
        float* o = Out + ((size_t)((bb * H + h) * T + t)) * DH + d;
        *(float4*)(o)     = make_float4(acc[i][0], acc[i][1], acc[i][2], acc[i][3]);
        *(float4*)(o + 4) = make_float4(acc[i][4], acc[i][5], acc[i][6], acc[i][7]);
    }
}

// ---------------------------------------------------------------------------
// Kernel 2: causal flash attention, fp32.
// Block = 64 query rows of one (b,h). 256 threads as 16x16, 4x4 per thread.
// smem: Qs[64][AW] (row-major), KP[..] (K as [d][s], reused for P as [r][s]),
// Vs[64][AW]. AW=68 padding -> conflict-free float4 gemm reads.
// ---------------------------------------------------------------------------
constexpr int AW = 68;
constexpr int ATTN_SMEM = 3 * 64 * AW * (int)sizeof(float);   // 52224 bytes

__global__ void __launch_bounds__(256, 1)
attn_kernel()
{
    extern __shared__ float sm[];
    float* Qs = sm;                 // [r][d]
    float* KP = sm + 64 * AW;       // K: [d][s]  ->  P: [r][s]
    float* Vs = sm + 2 * 64 * AW;   // [s][d]

    const int qblk = 15 - blockIdx.x;       // heavy tiles first
    const int bh   = blockIdx.y;            // b*H + h
    const int tid  = threadIdx.x;
    const int tx   = tid & 15;
    const int ty   = tid >> 4;

    const float* Qp = g_Q + ((size_t)bh * T + qblk * 64) * DH;

    for (int i = tid; i < 64 * 64; i += 256)
        Qs[(i >> 6) * AW + (i & 63)] = Qp[i];

    float m_r[4], l_r[4], O[4][4];
    #pragma unroll
    for (int i = 0; i < 4; i++) {
        m_r[i] = -1e30f; l_r[i] = 0.f;
        #pragma unroll
        for (int j = 0; j < 4; j++) O[i][j] = 0.f;
    }

    const float scale = 0.125f;   // DH^-0.5

    for (int jb = 0; jb <= qblk; jb++) {
        const float* Kp = g_K + ((size_t)bh * T + jb * 64) * DH;
        const float* Vp = g_V + ((size_t)bh * T + jb * 64) * DH;

        __syncthreads();   // prior iteration's KP/Vs reads complete
        for (int i = tid; i < 64 * 64; i += 256) {
            int s = i >> 6, d = i & 63;
            KP[d * AW + s] = Kp[i];     // transposed: [d][s]
            Vs[s * AW + d] = Vp[i];
        }
        __syncthreads();

        // S = Q * K^T   (thread owns rows r=ty*4+i, cols s=tx*4+j)
        float S[4][4] = {};
        #pragma unroll 8
        for (int d = 0; d < 64; d++) {
            float4 kv = *(const float4*)&KP[d * AW + tx * 4];
            #pragma unroll
            for (int i = 0; i < 4; i++) {
                float q = Qs[(ty * 4 + i) * AW + d];
                S[i][0] += q * kv.x;
                S[i][1] += q * kv.y;
                S[i][2] += q * kv.z;
                S[i][3] += q * kv.w;
            }
        }

        #pragma unroll
        for (int i = 0; i < 4; i++)
            #pragma unroll
            for (int j = 0; j < 4; j++)
                S[i][j] *= scale;

        if (jb == qblk) {   // causal mask on the diagonal tile
            #pragma unroll
            for (int i = 0; i < 4; i++)
                #pragma unroll
                for (int j = 0; j < 4; j++)
                    if (tx * 4 + j > ty * 4 + i) S[i][j] = -1e30f;
        }

        // Online softmax (row stats across the 16-lane tx group)
        #pragma unroll
        for (int i = 0; i < 4; i++) {
            float mx = fmaxf(fmaxf(S[i][0], S[i][1]), fmaxf(S[i][2], S[i][3]));
            #pragma unroll
            for (int off = 8; off; off >>= 1)
                mx = fmaxf(mx, __shfl_xor_sync(0xffffffffu, mx, off));
            float mnew  = fmaxf(m_r[i], mx);
            float alpha = __expf(m_r[i] - mnew);
            float rs = 0.f;
            #pragma unroll
            for (int j = 0; j < 4; j++) { S[i][j] = __expf(S[i][j] - mnew); rs += S[i][j]; }
            #pragma unroll
            for (int off = 8; off; off >>= 1)
                rs += __shfl_xor_sync(0xffffffffu, rs, off);
            l_r[i] = l_r[i] * alpha + rs;
            m_r[i] = mnew;
            #pragma unroll
            for (int j = 0; j < 4; j++) O[i][j] *= alpha;
        }

        __syncthreads();   // all K reads finished; KP becomes P
        #pragma unroll
        for (int i = 0; i < 4; i++)
            *(float4*)&KP[(ty * 4 + i) * AW + tx * 4] =
                make_float4(S[i][0], S[i][1], S[i][2], S[i][3]);
        __syncthreads();

        // O += P * V   (thread owns rows r=ty*4+i, d-cols tx*4+j)
        #pragma unroll 8
        for (int s = 0; s < 64; s++) {
            float4 v = *(const float4*)&Vs[s * AW + tx * 4];
            #pragma unroll
            for (int i = 0; i < 4; i++) {
                float p = KP[(ty * 4 + i) * AW + s];
                O[i][0] += p * v.x;
                O[i][1] += p * v.y;
                O[i][2] += p * v.z;
                O[i][3] += p * v.w;
            }
        }
    }

    // Epilogue: normalize and write [b*T+t][h*DH+d]
    const int b = bh >> 4, h = bh & 15;
    #pragma unroll
    for (int i = 0; i < 4; i++) {
        float inv = 1.0f / l_r[i];
        int t = qblk * 64 + ty * 4 + i;
        *(float4*)&g_O[((size_t)(b * T + t)) * HD + h * DH + tx * 4] =
            make_float4(O[i][0] * inv, O[i][1] * inv, O[i][2] * inv, O[i][3] * inv);
    }
}

// ---------------------------------------------------------------------------
// Kernel 3: output projection.  out[M, E] = g_O[M, HD] * Wo^T + bo
// NT GEMM: both operands K-contiguous. Same SGEMM skeleton.
// ---------------------------------------------------------------------------
__global__ void __launch_bounds__(256, 2)
outproj_kernel(const float* __restrict__ Wo,
               const float* __restrict__ bo,
               float* __restrict__ out)
{
    __shared__ float As[8][128];
    __shared__ float Bs[8][128];

    const int m0 = blockIdx.x * 128;
    const int n0 = blockIdx.y * 128;

    const int tid = threadIdx.x;
    const int tx  = tid & 15;
    const int ty  = tid >> 4;
    const int rowA = tid >> 1;
    const int colA = (tid & 1) * 4;

    float acc[8][8] = {};

    const float* Aptr = g_O + (size_t)(m0 + rowA) * HD + colA;
    const float* Bptr = Wo  + (size_t)(n0 + rowA) * HD + colA;

    for (int k0 = 0; k0 < HD; k0 += 8) {
        float4 av = *(const float4*)(Aptr + k0);
        As[colA + 0][rowA] = av.x;
        As[colA + 1][rowA] = av.y;
        As[colA + 2][rowA] = av.z;
        As[colA + 3][rowA] = av.w;

        float4 bv = *(const float4*)(Bptr + k0);
        Bs[colA + 0][rowA] = bv.x;
        Bs[colA + 1][rowA] = bv.y;
        Bs[colA + 2][rowA] = bv.z;
        Bs[colA + 3][rowA] = bv.w;
        __syncthreads();

        #pragma unroll
        for (int k = 0; k < 8; k++) {
            float4 a0 = *(const float4*)&As[k][ty * 8];
            float4 a1 = *(const float4*)&As[k][ty * 8 + 4];
            float4 b0 = *(const float4*)&Bs[k][tx * 8];
            float4 b1 = *(const float4*)&Bs[k][tx * 8 + 4];
            float a[8] = {a0.x, a0.y, a0.z, a0.w, a1.x, a1.y, a1.z, a1.w};
            float b[8] = {b0.x, b0.y, b0.z, b0.w, b1.x, b1.y, b1.z, b1.w};
            #pragma unroll
            for (int i = 0; i < 8; i++)
                #pragma unroll
                for (int j = 0; j < 8; j++)
                    acc[i][j] += a[i] * b[j];
        }
        __syncthreads();
    }

    float4 bias0 = *(const float4*)&bo[n0 + tx * 8];
    float4 bias1 = *(const float4*)&bo[n0 + tx * 8 + 4];
    #pragma unroll
    for (int i = 0; i < 8; i++) {
        float* o = out + (size_t)(m0 + ty * 8 + i) * E + n0 + tx * 8;
        *(float4*)(o)     = make_float4(acc[i][0] + bias0.x, acc[i][1] + bias0.y,
                                        acc[i][2] + bias0.z, acc[i][3] + bias0.w);
        *(float4*)(o + 4) = make_float4(acc[i][4] + bias1.x, acc[i][5] + bias1.y,
                                        acc[i][6] + bias1.z, acc[i][7] + bias1.w);
    }
}

// ---------------------------------------------------------------------------
extern "C" void kernel_launch(void* const* d_in, const int* in_sizes, int n_in,
                              void* d_out, int out_size)
{
    const float* x  = (const float*)d_in[0];
    const float* Wq = (const float*)d_in[1];
    const float* Wk = (const float*)d_in[2];
    const float* Wv = (const float*)d_in[3];
    const float* Wo = (const float*)d_in[4];
    const float* bo = (const float*)d_in[5];
    float* out = (float*)d_out;

    (void)in_sizes; (void)n_in; (void)out_size;

    // Idempotent attribute set; not a stream op, legal under graph capture.
    cudaFuncSetAttribute(attn_kernel,
                         cudaFuncAttributeMaxDynamicSharedMemorySize, ATTN_SMEM);

    qkv_kernel<<<dim3(M / 128, 24), 256>>>(x, Wq, Wk, Wv);
    attn_kernel<<<dim3(T / 64, B * H), 256, ATTN_SMEM>>>();
    outproj_kernel<<<dim3(M / 128, E / 128), 256>>>(Wo, bo, out);
}

// round 4
// speedup vs baseline: 1.2657x; 1.2657x over previous
#include <cuda_runtime.h>
#include <cuda_bf16.h>
#include <cstdint>

// Problem constants
constexpr int B  = 4;
constexpr int T  = 1024;
constexpr int E  = 1024;
constexpr int H  = 16;
constexpr int DH = 64;
constexpr int M  = B * T;        // 4096
constexpr int HD = H * DH;       // 1024

// Scratch
__device__ float g_Q[B * H * T * DH];   // [b][h][t][d]
__device__ float g_K[B * H * T * DH];
__device__ float g_V[B * H * T * DH];
__device__ float g_O[M * HD];           // [b*T+t][h*DH+d]

// ---------------------------------------------------------------------------
// mma.sync helpers (compute_100-safe: sm_80-era PTX)
// ---------------------------------------------------------------------------
__device__ __forceinline__ uint32_t smem_u32(const void* p) {
    uint32_t a;
    asm("{ .reg .u64 t; cvta.to.shared.u64 t, %1; cvt.u32.u64 %0, t; }" : "=r"(a) : "l"(p));
    return a;
}

__device__ __forceinline__ void ldsm_x4(uint32_t& r0, uint32_t& r1, uint32_t& r2, uint32_t& r3,
                                        uint32_t addr) {
    asm volatile("ldmatrix.sync.aligned.m8n8.x4.shared.b16 {%0,%1,%2,%3}, [%4];"
                 : "=r"(r0), "=r"(r1), "=r"(r2), "=r"(r3) : "r"(addr));
}
__device__ __forceinline__ void ldsm_x2(uint32_t& r0, uint32_t& r1, uint32_t addr) {
    asm volatile("ldmatrix.sync.aligned.m8n8.x2.shared.b16 {%0,%1}, [%2];"
                 : "=r"(r0), "=r"(r1) : "r"(addr));
}
__device__ __forceinline__ void mma_bf16(float* c, const uint32_t* a, const uint32_t* b) {
    asm volatile(
        "mma.sync.aligned.m16n8k16.row.col.f32.bf16.bf16.f32 "
        "{%0,%1,%2,%3}, {%4,%5,%6,%7}, {%8,%9}, {%0,%1,%2,%3};"
        : "+f"(c[0]), "+f"(c[1]), "+f"(c[2]), "+f"(c[3])
        : "r"(a[0]), "r"(a[1]), "r"(a[2]), "r"(a[3]), "r"(b[0]), "r"(b[1]));
}

// hi/lo bf16 split of two consecutive floats -> packed u32s
__device__ __forceinline__ void split2(float a, float b, uint32_t& hi, uint32_t& lo) {
    __nv_bfloat16 ha = __float2bfloat16(a), hb = __float2bfloat16(b);
    __nv_bfloat16 la = __float2bfloat16(a - __bfloat162float(ha));
    __nv_bfloat16 lb = __float2bfloat16(b - __bfloat162float(hb));
    hi = (uint32_t)__bfloat16_as_ushort(ha) | ((uint32_t)__bfloat16_as_ushort(hb) << 16);
    lo = (uint32_t)__bfloat16_as_ushort(la) | ((uint32_t)__bfloat16_as_ushort(lb) << 16);
}

// GEMM tiling
constexpr int BK  = 32;
constexpr int PK  = 40;                  // padded row stride (bf16): 80B -> conflict-free ldmatrix

// ---------------------------------------------------------------------------
// GEMM core: computes a 128x128 tile of A(128,K) * B(128,K)^T with hi/lo split.
// A rows contiguous-K. Warp grid 2x4 (warp tile 64x32). Accum c[4][4][4].
// loadB is a lambda-ish macro responsibility of the caller; here both kernels
// inline their own loaders around gemm_mainloop_step.
// ---------------------------------------------------------------------------
struct Frag { uint32_t a[4]; };

__device__ __forceinline__ void gemm_compute(const __nv_bfloat16* sAh, const __nv_bfloat16* sAl,
                                             const __nv_bfloat16* sBh, const __nv_bfloat16* sBl,
                                             float c[4][4][4], int lane, int wy, int wx) {
    const uint32_t aH = smem_u32(sAh), aL = smem_u32(sAl);
    const uint32_t bH = smem_u32(sBh), bL = smem_u32(sBl);
    const int arow = wy * 64 + (lane & 15);
    const int acol8 = (lane >> 4) * 8;
    const int brow = wx * 32 + (lane & 7);
    const int bcol8 = ((lane >> 3) & 1) * 8;

    #pragma unroll
    for (int ks = 0; ks < 2; ks++) {
        const int k0 = ks * 16;
        uint32_t Ah[4][4], Al[4][4], Bh[4][2], Bl[4][2];
        #pragma unroll
        for (int mi = 0; mi < 4; mi++) {
            uint32_t off = ((arow + mi * 16) * PK + k0 + acol8) * 2;
            ldsm_x4(Ah[mi][0], Ah[mi][1], Ah[mi][2], Ah[mi][3], aH + off);
            ldsm_x4(Al[mi][0], Al[mi][1], Al[mi][2], Al[mi][3], aL + off);
        }
        #pragma unroll
        for (int ni = 0; ni < 4; ni++) {
            uint32_t off = ((brow + ni * 8) * PK + k0 + bcol8) * 2;
            ldsm_x2(Bh[ni][0], Bh[ni][1], bH + off);
            ldsm_x2(Bl[ni][0], Bl[ni][1], bL + off);
        }
        #pragma unroll
        for (int mi = 0; mi < 4; mi++)
            #pragma unroll
            for (int ni = 0; ni < 4; ni++) {
                mma_bf16(c[mi][ni], Ah[mi], Bh[ni]);
                mma_bf16(c[mi][ni], Ah[mi], Bl[ni]);
                mma_bf16(c[mi][ni], Al[mi], Bh[ni]);
            }
    }
}

// Load a 128-row x 32-k fp32 block (row stride ld) into split smem tiles.
__device__ __forceinline__ void load_rows_split(const float* src, int ld, int k0,
                                                __nv_bfloat16* sH, __nv_bfloat16* sL, int tid) {
    #pragma unroll
    for (int j = 0; j < 4; j++) {
        int flat = j * 256 + tid;
        int r  = flat >> 3;
        int kq = (flat & 7) * 4;
        float4 v = *(const float4*)(src + (size_t)r * ld + k0 + kq);
        uint32_t h01, l01, h23, l23;
        split2(v.x, v.y, h01, l01);
        split2(v.z, v.w, h23, l23);
        *(uint32_t*)(sH + r * PK + kq)     = h01;
        *(uint32_t*)(sH + r * PK + kq + 2) = h23;
        *(uint32_t*)(sL + r * PK + kq)     = l01;
        *(uint32_t*)(sL + r * PK + kq + 2) = l23;
    }
}

// ---------------------------------------------------------------------------
// Kernel 1: QKV projection via mma.sync (hi/lo bf16 split)
// ---------------------------------------------------------------------------
__global__ void __launch_bounds__(256, 2)
qkv_mma(const float* __restrict__ x,
        const float* __restrict__ Wq,
        const float* __restrict__ Wk,
        const float* __restrict__ Wv)
{
    __shared__ __align__(16) __nv_bfloat16 sAh[128 * PK], sAl[128 * PK];
    __shared__ __align__(16) __nv_bfloat16 sBh[128 * PK], sBl[128 * PK];

    const int tid  = threadIdx.x;
    const int lane = tid & 31;
    const int wid  = tid >> 5;
    const int wy = wid >> 2, wx = wid & 3;

    const int m0   = blockIdx.x * 128;
    const int nblk = blockIdx.y;
    const int sel  = nblk >> 3;
    const int nn0  = (nblk & 7) * 128;
    const float* Wsel = (sel == 0) ? Wq : (sel == 1) ? Wk : Wv;
    float*       Out  = (sel == 0) ? g_Q : (sel == 1) ? g_K : g_V;

    float c[4][4][4] = {};

    for (int k0 = 0; k0 < E; k0 += BK) {
        load_rows_split(x + (size_t)m0 * E, E, k0, sAh, sAl, tid);
        // B tile: Bs[n][k] from Wsel[h][e=k][d]
        #pragma unroll
        for (int j = 0; j < 4; j++) {
            int flat = j * 256 + tid;
            int k  = flat >> 5;
            int n  = (flat & 31) * 4;
            int ng = nn0 + n;
            int h  = ng >> 6, d = ng & 63;
            float4 v = *(const float4*)(Wsel + ((size_t)(h * E + k0 + k)) * DH + d);
            float vv[4] = {v.x, v.y, v.z, v.w};
            #pragma unroll
            for (int i = 0; i < 4; i++) {
                __nv_bfloat16 hv = __float2bfloat16(vv[i]);
                __nv_bfloat16 lv = __float2bfloat16(vv[i] - __bfloat162float(hv));
                sBh[(n + i) * PK + k] = hv;
                sBl[(n + i) * PK + k] = lv;
            }
        }
        __syncthreads();
        gemm_compute(sAh, sAl, sBh, sBl, c, lane, wy, wx);
        __syncthreads();
    }

    // Epilogue: scatter into [b][h][t][d]
    const int g = lane >> 2, tg = lane & 3;
    #pragma unroll
    for (int mi = 0; mi < 4; mi++) {
        #pragma unroll
        for (int half = 0; half < 2; half++) {
            int m  = m0 + wy * 64 + mi * 16 + g + half * 8;
            int bb = m >> 10, t = m & 1023;
            #pragma unroll
            for (int ni = 0; ni < 4; ni++) {
                int n = nn0 + wx * 32 + ni * 8 + tg * 2;
                int h = n >> 6, d = n & 63;
                float2 val = make_float2(c[mi][ni][half * 2], c[mi][ni][half * 2 + 1]);
                *(float2*)(Out + ((size_t)((bb * H + h) * T + t)) * DH + d) = val;
            }
        }
    }
}

// ---------------------------------------------------------------------------
// Kernel 3: output projection via mma.sync.  out = g_O * Wo^T + bo  (NT)
// ---------------------------------------------------------------------------
__global__ void __launch_bounds__(256, 2)
outproj_mma(const float* __restrict__ Wo,
            const float* __restrict__ bo,
            float* __restrict__ out)
{
    __shared__ __align__(16) __nv_bfloat16 sAh[128 * PK], sAl[128 * PK];
    __shared__ __align__(16) __nv_bfloat16 sBh[128 * PK], sBl[128 * PK];

    const int tid  = threadIdx.x;
    const int lane = tid & 31;
    const int wid  = tid >> 5;
    const int wy = wid >> 2, wx = wid & 3;

    const int m0 = blockIdx.x * 128;
    const int n0 = blockIdx.y * 128;

    float c[4][4][4] = {};

    for (int k0 = 0; k0 < HD; k0 += BK) {
        load_rows_split(g_O + (size_t)m0 * HD, HD, k0, sAh, sAl, tid);
        load_rows_split(Wo  + (size_t)n0 * HD, HD, k0, sBh, sBl, tid);
        __syncthreads();
        gemm_compute(sAh, sAl, sBh, sBl, c, lane, wy, wx);
        __syncthreads();
    }

    const int g = lane >> 2, tg = lane & 3;
    #pragma unroll
    for (int mi = 0; mi < 4; mi++) {
        #pragma unroll
        for (int half = 0; half < 2; half++) {
            int m = m0 + wy * 64 + mi * 16 + g + half * 8;
            #pragma unroll
            for (int ni = 0; ni < 4; ni++) {
                int n = n0 + wx * 32 + ni * 8 + tg * 2;
                float2 bv = *(const float2*)(bo + n);
                float2 val = make_float2(c[mi][ni][half * 2] + bv.x,
                                         c[mi][ni][half * 2 + 1] + bv.y);
                *(float2*)(out + (size_t)m * E + n) = val;
            }
        }
    }
}

// ---------------------------------------------------------------------------
// Kernel 2: causal flash attention, fp32 (unchanged from passing baseline)
// ---------------------------------------------------------------------------
constexpr int AW = 68;
constexpr int ATTN_SMEM = 3 * 64 * AW * (int)sizeof(float);   // 52224

__global__ void __launch_bounds__(256, 1)
attn_kernel()
{
    extern __shared__ float smf[];
    float* Qs = smf;
    float* KP = smf + 64 * AW;
    float* Vs = smf + 2 * 64 * AW;

    const int qblk = 15 - blockIdx.x;
    const int bh   = blockIdx.y;
    const int tid  = threadIdx.x;
    const int tx   = tid & 15;
    const int ty   = tid >> 4;

    const float* Qp = g_Q + ((size_t)bh * T + qblk * 64) * DH;
    for (int i = tid; i < 64 * 64; i += 256)
        Qs[(i >> 6) * AW + (i & 63)] = Qp[i];

    float m_r[4], l_r[4], O[4][4];
    #pragma unroll
    for (int i = 0; i < 4; i++) {
        m_r[i] = -1e30f; l_r[i] = 0.f;
        #pragma unroll
        for (int j = 0; j < 4; j++) O[i][j] = 0.f;
    }
    const float scale = 0.125f;

    for (int jb = 0; jb <= qblk; jb++) {
        const float* Kp = g_K + ((size_t)bh * T + jb * 64) * DH;
        const float* Vp = g_V + ((size_t)bh * T + jb * 64) * DH;
        __syncthreads();
        for (int i = tid; i < 64 * 64; i += 256) {
            int s = i >> 6, d = i & 63;
            KP[d * AW + s] = Kp[i];
            Vs[s * AW + d] = Vp[i];
        }
        __syncthreads();

        float S[4][4] = {};
        #pragma unroll 8
        for (int d = 0; d < 64; d++) {
            float4 kv = *(const float4*)&KP[d * AW + tx * 4];
            #pragma unroll
            for (int i = 0; i < 4; i++) {
                float q = Qs[(ty * 4 + i) * AW + d];
                S[i][0] += q * kv.x; S[i][1] += q * kv.y;
                S[i][2] += q * kv.z; S[i][3] += q * kv.w;
            }
        }
        #pragma unroll
        for (int i = 0; i < 4; i++)
            #pragma unroll
            for (int j = 0; j < 4; j++) S[i][j] *= scale;

        if (jb == qblk) {
            #pragma unroll
            for (int i = 0; i < 4; i++)
                #pragma unroll
                for (int j = 0; j < 4; j++)
                    if (tx * 4 + j > ty * 4 + i) S[i][j] = -1e30f;
        }
        #pragma unroll
        for (int i = 0; i < 4; i++) {
            float mx = fmaxf(fmaxf(S[i][0], S[i][1]), fmaxf(S[i][2], S[i][3]));
            #pragma unroll
            for (int off = 8; off; off >>= 1)
                mx = fmaxf(mx, __shfl_xor_sync(0xffffffffu, mx, off));
            float mnew  = fmaxf(m_r[i], mx);
            float alpha = __expf(m_r[i] - mnew);
            float rs = 0.f;
            #pragma unroll
            for (int j = 0; j < 4; j++) { S[i][j] = __expf(S[i][j] - mnew); rs += S[i][j]; }
            #pragma unroll
            for (int off = 8; off; off >>= 1)
                rs += __shfl_xor_sync(0xffffffffu, rs, off);
            l_r[i] = l_r[i] * alpha + rs;
            m_r[i] = mnew;
            #pragma unroll
            for (int j = 0; j < 4; j++) O[i][j] *= alpha;
        }
        __syncthreads();
        #pragma unroll
        for (int i = 0; i < 4; i++)
            *(float4*)&KP[(ty * 4 + i) * AW + tx * 4] =
                make_float4(S[i][0], S[i][1], S[i][2], S[i][3]);
        __syncthreads();
        #pragma unroll 8
        for (int s = 0; s < 64; s++) {
            float4 v = *(const float4*)&Vs[s * AW + tx * 4];
            #pragma unroll
            for (int i = 0; i < 4; i++) {
                float p = KP[(ty * 4 + i) * AW + s];
                O[i][0] += p * v.x; O[i][1] += p * v.y;
                O[i][2] += p * v.z; O[i][3] += p * v.w;
            }
        }
    }
    const int b = bh >> 4, h = bh & 15;
    #pragma unroll
    for (int i = 0; i < 4; i++) {
        float inv = 1.0f / l_r[i];
        int t = qblk * 64 + ty * 4 + i;
        *(float4*)&g_O[((size_t)(b * T + t)) * HD + h * DH + tx * 4] =
            make_float4(O[i][0] * inv, O[i][1] * inv, O[i][2] * inv, O[i][3] * inv);
    }
}

// ---------------------------------------------------------------------------
extern "C" void kernel_launch(void* const* d_in, const int* in_sizes, int n_in,
                              void* d_out, int out_size)
{
    const float* x  = (const float*)d_in[0];
    const float* Wq = (const float*)d_in[1];
    const float* Wk = (const float*)d_in[2];
    const float* Wv = (const float*)d_in[3];
    const float* Wo = (const float*)d_in[4];
    const float* bo = (const float*)d_in[5];
    float* out = (float*)d_out;
    (void)in_sizes; (void)n_in; (void)out_size;

    cudaFuncSetAttribute(attn_kernel, cudaFuncAttributeMaxDynamicSharedMemorySize, ATTN_SMEM);

    qkv_mma<<<dim3(M / 128, 24), 256>>>(x, Wq, Wk, Wv);
    attn_kernel<<<dim3(T / 64, B * H), 256, ATTN_SMEM>>>();
    outproj_mma<<<dim3(M / 128, E / 128), 256>>>(Wo, bo, out);
}

// round 5
// speedup vs baseline: 1.9548x; 1.5445x over previous
#include <cuda_runtime.h>
#include <cuda_bf16.h>
#include <cstdint>

// Problem constants
constexpr int B  = 4;
constexpr int T  = 1024;
constexpr int E  = 1024;
constexpr int H  = 16;
constexpr int DH = 64;
constexpr int M  = B * T;        // 4096
constexpr int HD = H * DH;       // 1024

// Scratch
__device__ float g_Q[B * H * T * DH];   // [b][h][t][d]
__device__ float g_K[B * H * T * DH];
__device__ float g_V[B * H * T * DH];
__device__ float g_O[M * HD];           // [b*T+t][h*DH+d]

// ---------------------------------------------------------------------------
// mma.sync helpers (compute_100-safe: sm_80-era PTX)
// ---------------------------------------------------------------------------
__device__ __forceinline__ uint32_t smem_u32(const void* p) {
    uint32_t a;
    asm("{ .reg .u64 t; cvta.to.shared.u64 t, %1; cvt.u32.u64 %0, t; }" : "=r"(a) : "l"(p));
    return a;
}
__device__ __forceinline__ void ldsm_x4(uint32_t& r0, uint32_t& r1, uint32_t& r2, uint32_t& r3,
                                        uint32_t addr) {
    asm volatile("ldmatrix.sync.aligned.m8n8.x4.shared.b16 {%0,%1,%2,%3}, [%4];"
                 : "=r"(r0), "=r"(r1), "=r"(r2), "=r"(r3) : "r"(addr));
}
__device__ __forceinline__ void ldsm_x2(uint32_t& r0, uint32_t& r1, uint32_t addr) {
    asm volatile("ldmatrix.sync.aligned.m8n8.x2.shared.b16 {%0,%1}, [%2];"
                 : "=r"(r0), "=r"(r1) : "r"(addr));
}
__device__ __forceinline__ void ldsm_x2_t(uint32_t& r0, uint32_t& r1, uint32_t addr) {
    asm volatile("ldmatrix.sync.aligned.m8n8.x2.trans.shared.b16 {%0,%1}, [%2];"
                 : "=r"(r0), "=r"(r1) : "r"(addr));
}
__device__ __forceinline__ void mma_bf16(float* c, const uint32_t* a, const uint32_t* b) {
    asm volatile(
        "mma.sync.aligned.m16n8k16.row.col.f32.bf16.bf16.f32 "
        "{%0,%1,%2,%3}, {%4,%5,%6,%7}, {%8,%9}, {%0,%1,%2,%3};"
        : "+f"(c[0]), "+f"(c[1]), "+f"(c[2]), "+f"(c[3])
        : "r"(a[0]), "r"(a[1]), "r"(a[2]), "r"(a[3]), "r"(b[0]), "r"(b[1]));
}

// hi/lo bf16 split of two floats -> packed u32s
__device__ __forceinline__ void split2(float a, float b, uint32_t& hi, uint32_t& lo) {
    __nv_bfloat16 ha = __float2bfloat16(a), hb = __float2bfloat16(b);
    __nv_bfloat16 la = __float2bfloat16(a - __bfloat162float(ha));
    __nv_bfloat16 lb = __float2bfloat16(b - __bfloat162float(hb));
    hi = (uint32_t)__bfloat16_as_ushort(ha) | ((uint32_t)__bfloat16_as_ushort(hb) << 16);
    lo = (uint32_t)__bfloat16_as_ushort(la) | ((uint32_t)__bfloat16_as_ushort(lb) << 16);
}

// GEMM tiling
constexpr int BK  = 32;
constexpr int NK  = 32;                   // 1024 / BK
constexpr int PK  = 40;                   // [row][k] padded k-stride (bf16)
constexpr int PKN = 136;                  // qkv B [k][n] padded n-stride (bf16)
constexpr int TA_BYTES  = 128 * PK * 2;   // 10240 per tile
constexpr int BUF_BYTES = 4 * TA_BYTES;   // Ah, Al, Bh, Bl
constexpr int GEMM_SMEM = 2 * BUF_BYTES;  // 81920 (double buffer)

// ---------------------------------------------------------------------------
// Loaders
// ---------------------------------------------------------------------------
__device__ __forceinline__ void prefA(const float* src, int ld, int k0, float4 rA[4], int tid) {
    #pragma unroll
    for (int j = 0; j < 4; j++) {
        int flat = j * 256 + tid;
        int r = flat >> 3, kq = (flat & 7) * 4;
        rA[j] = *(const float4*)(src + (size_t)r * ld + k0 + kq);
    }
}
__device__ __forceinline__ void storeA(const float4 rA[4], char* buf, int tid) {
    __nv_bfloat16* sH = (__nv_bfloat16*)buf;
    __nv_bfloat16* sL = (__nv_bfloat16*)(buf + TA_BYTES);
    #pragma unroll
    for (int j = 0; j < 4; j++) {
        int flat = j * 256 + tid;
        int r = flat >> 3, kq = (flat & 7) * 4;
        uint32_t h01, l01, h23, l23;
        split2(rA[j].x, rA[j].y, h01, l01);
        split2(rA[j].z, rA[j].w, h23, l23);
        *(uint32_t*)(sH + r * PK + kq)     = h01;
        *(uint32_t*)(sH + r * PK + kq + 2) = h23;
        *(uint32_t*)(sL + r * PK + kq)     = l01;
        *(uint32_t*)(sL + r * PK + kq + 2) = l23;
    }
}
// direct load+split+store of 128 rows x BK k into [row][k] tiles (outproj B)
__device__ __forceinline__ void loadB_rows(const float* src, int ld, int k0, char* buf, int tid) {
    __nv_bfloat16* sH = (__nv_bfloat16*)(buf + 2 * TA_BYTES);
    __nv_bfloat16* sL = (__nv_bfloat16*)(buf + 3 * TA_BYTES);
    #pragma unroll
    for (int j = 0; j < 4; j++) {
        int flat = j * 256 + tid;
        int r = flat >> 3, kq = (flat & 7) * 4;
        float4 v = *(const float4*)(src + (size_t)r * ld + k0 + kq);
        uint32_t h01, l01, h23, l23;
        split2(v.x, v.y, h01, l01);
        split2(v.z, v.w, h23, l23);
        *(uint32_t*)(sH + r * PK + kq)     = h01;
        *(uint32_t*)(sH + r * PK + kq + 2) = h23;
        *(uint32_t*)(sL + r * PK + kq)     = l01;
        *(uint32_t*)(sL + r * PK + kq + 2) = l23;
    }
}
// qkv B: W[h][e][d] gather -> [k][n] tiles (contiguous-n u32 stores, 2-way conflicts)
__device__ __forceinline__ void loadB_qkv(const float* Wsel, int nn0, int k0, char* buf, int tid) {
    __nv_bfloat16* sH = (__nv_bfloat16*)(buf + 2 * TA_BYTES);
    __nv_bfloat16* sL = (__nv_bfloat16*)(buf + 3 * TA_BYTES);
    #pragma unroll
    for (int j = 0; j < 2; j++) {
        int flat = j * 256 + tid;
        int k  = (flat >> 5) * 2;
        int n4 = (flat & 31) * 4;
        int ng = nn0 + n4;
        int h = ng >> 6, d = ng & 63;
        const float* base = Wsel + ((size_t)(h * E + k0 + k)) * DH + d;
        float4 v0 = *(const float4*)base;
        float4 v1 = *(const float4*)(base + DH);
        uint32_t h01, l01, h23, l23;
        split2(v0.x, v0.y, h01, l01);
        split2(v0.z, v0.w, h23, l23);
        *(uint32_t*)(sH + k * PKN + n4)     = h01;
        *(uint32_t*)(sH + k * PKN + n4 + 2) = h23;
        *(uint32_t*)(sL + k * PKN + n4)     = l01;
        *(uint32_t*)(sL + k * PKN + n4 + 2) = l23;
        split2(v1.x, v1.y, h01, l01);
        split2(v1.z, v1.w, h23, l23);
        *(uint32_t*)(sH + (k + 1) * PKN + n4)     = h01;
        *(uint32_t*)(sH + (k + 1) * PKN + n4 + 2) = h23;
        *(uint32_t*)(sL + (k + 1) * PKN + n4)     = l01;
        *(uint32_t*)(sL + (k + 1) * PKN + n4 + 2) = l23;
    }
}

// ---------------------------------------------------------------------------
// Compute core: 128x128 tile, warp grid 2x4 (warp tile 64x32), 3-term split.
// BT = true: B stored [k][n] (PKN), read via ldmatrix.trans (qkv)
// BT = false: B stored [n][k] (PK), read via ldmatrix (outproj)
// ---------------------------------------------------------------------------
template <bool BT>
__device__ __forceinline__ void gemm_compute(char* buf, float c[4][4][4],
                                             int lane, int wy, int wx) {
    const uint32_t aH = smem_u32(buf);
    const uint32_t aL = aH + TA_BYTES;
    const uint32_t bH = aH + 2 * TA_BYTES;
    const uint32_t bL = aH + 3 * TA_BYTES;
    const int arow  = wy * 64 + (lane & 15);
    const int acol8 = (lane >> 4) * 8;

    #pragma unroll
    for (int ks = 0; ks < 2; ks++) {
        const int k0 = ks * 16;
        uint32_t Bh[4][2], Bl[4][2];
        if (BT) {
            const int krow = k0 + (lane & 15);
            #pragma unroll
            for (int ni = 0; ni < 4; ni++) {
                uint32_t off = (uint32_t)(krow * PKN + wx * 32 + ni * 8) * 2;
                ldsm_x2_t(Bh[ni][0], Bh[ni][1], bH + off);
                ldsm_x2_t(Bl[ni][0], Bl[ni][1], bL + off);
            }
        } else {
            const int brow  = wx * 32 + (lane & 7);
            const int bcol8 = ((lane >> 3) & 1) * 8;
            #pragma unroll
            for (int ni = 0; ni < 4; ni++) {
                uint32_t off = (uint32_t)((brow + ni * 8) * PK + k0 + bcol8) * 2;
                ldsm_x2(Bh[ni][0], Bh[ni][1], bH + off);
                ldsm_x2(Bl[ni][0], Bl[ni][1], bL + off);
            }
        }
        #pragma unroll
        for (int mi = 0; mi < 4; mi++) {
            uint32_t Ah[4], Al[4];
            uint32_t off = (uint32_t)((arow + mi * 16) * PK + k0 + acol8) * 2;
            ldsm_x4(Ah[0], Ah[1], Ah[2], Ah[3], aH + off);
            ldsm_x4(Al[0], Al[1], Al[2], Al[3], aL + off);
            #pragma unroll
            for (int ni = 0; ni < 4; ni++) {
                mma_bf16(c[mi][ni], Ah, Bh[ni]);
                mma_bf16(c[mi][ni], Ah, Bl[ni]);
                mma_bf16(c[mi][ni], Al, Bh[ni]);
            }
        }
    }
}

// ---------------------------------------------------------------------------
// Kernel 1: QKV projection (pipelined, double-buffered)
// ---------------------------------------------------------------------------
__global__ void __launch_bounds__(256, 2)
qkv_mma(const float* __restrict__ x,
        const float* __restrict__ Wq,
        const float* __restrict__ Wk,
        const float* __restrict__ Wv)
{
    extern __shared__ char smbuf[];
    const int tid  = threadIdx.x;
    const int lane = tid & 31;
    const int wid  = tid >> 5;
    const int wy = wid >> 2, wx = wid & 3;

    const int m0   = blockIdx.x * 128;
    const int nblk = blockIdx.y;
    const int sel  = nblk >> 3;
    const int nn0  = (nblk & 7) * 128;
    const float* Wsel = (sel == 0) ? Wq : (sel == 1) ? Wk : Wv;
    float*       Out  = (sel == 0) ? g_Q : (sel == 1) ? g_K : g_V;

    float c[4][4][4] = {};
    float4 rA[4];
    prefA(x + (size_t)m0 * E, E, 0, rA, tid);

    for (int kt = 0; kt < NK; kt++) {
        char* buf = smbuf + (kt & 1) * BUF_BYTES;
        storeA(rA, buf, tid);
        loadB_qkv(Wsel, nn0, kt * BK, buf, tid);
        __syncthreads();
        if (kt + 1 < NK) prefA(x + (size_t)m0 * E, E, (kt + 1) * BK, rA, tid);
        gemm_compute<true>(buf, c, lane, wy, wx);
    }

    // Epilogue: scatter into [b][h][t][d]
    const int g = lane >> 2, tg = lane & 3;
    #pragma unroll
    for (int mi = 0; mi < 4; mi++) {
        #pragma unroll
        for (int half = 0; half < 2; half++) {
            int m  = m0 + wy * 64 + mi * 16 + g + half * 8;
            int bb = m >> 10, t = m & 1023;
            #pragma unroll
            for (int ni = 0; ni < 4; ni++) {
                int n = nn0 + wx * 32 + ni * 8 + tg * 2;
                int h = n >> 6, d = n & 63;
                float2 val = make_float2(c[mi][ni][half * 2], c[mi][ni][half * 2 + 1]);
                *(float2*)(Out + ((size_t)((bb * H + h) * T + t)) * DH + d) = val;
            }
        }
    }
}

// ---------------------------------------------------------------------------
// Kernel 3: output projection (pipelined, double-buffered).  out = g_O*Wo^T+bo
// ---------------------------------------------------------------------------
__global__ void __launch_bounds__(256, 2)
outproj_mma(const float* __restrict__ Wo,
            const float* __restrict__ bo,
            float* __restrict__ out)
{
    extern __shared__ char smbuf[];
    const int tid  = threadIdx.x;
    const int lane = tid & 31;
    const int wid  = tid >> 5;
    const int wy = wid >> 2, wx = wid & 3;

    const int m0 = blockIdx.x * 128;
    const int n0 = blockIdx.y * 128;

    float c[4][4][4] = {};
    float4 rA[4];
    prefA(g_O + (size_t)m0 * HD, HD, 0, rA, tid);

    for (int kt = 0; kt < NK; kt++) {
        char* buf = smbuf + (kt & 1) * BUF_BYTES;
        storeA(rA, buf, tid);
        loadB_rows(Wo + (size_t)n0 * HD, HD, kt * BK, buf, tid);
        __syncthreads();
        if (kt + 1 < NK) prefA(g_O + (size_t)m0 * HD, HD, (kt + 1) * BK, rA, tid);
        gemm_compute<false>(buf, c, lane, wy, wx);
    }

    const int g = lane >> 2, tg = lane & 3;
    #pragma unroll
    for (int mi = 0; mi < 4; mi++) {
        #pragma unroll
        for (int half = 0; half < 2; half++) {
            int m = m0 + wy * 64 + mi * 16 + g + half * 8;
            #pragma unroll
            for (int ni = 0; ni < 4; ni++) {
                int n = n0 + wx * 32 + ni * 8 + tg * 2;
                float2 bv = *(const float2*)(bo + n);
                float2 val = make_float2(c[mi][ni][half * 2] + bv.x,
                                         c[mi][ni][half * 2 + 1] + bv.y);
                *(float2*)(out + (size_t)m * E + n) = val;
            }
        }
    }
}

// ---------------------------------------------------------------------------
// Kernel 2: causal flash attention, fp32 (unchanged — validated)
// ---------------------------------------------------------------------------
constexpr int AW = 68;
constexpr int ATTN_SMEM = 3 * 64 * AW * (int)sizeof(float);   // 52224

__global__ void __launch_bounds__(256, 1)
attn_kernel()
{
    extern __shared__ float smf[];
    float* Qs = smf;
    float* KP = smf + 64 * AW;
    float* Vs = smf + 2 * 64 * AW;

    const int qblk = 15 - blockIdx.x;
    const int bh   = blockIdx.y;
    const int tid  = threadIdx.x;
    const int tx   = tid & 15;
    const int ty   = tid >> 4;

    const float* Qp = g_Q + ((size_t)bh * T + qblk * 64) * DH;
    for (int i = tid; i < 64 * 64; i += 256)
        Qs[(i >> 6) * AW + (i & 63)] = Qp[i];

    float m_r[4], l_r[4], O[4][4];
    #pragma unroll
    for (int i = 0; i < 4; i++) {
        m_r[i] = -1e30f; l_r[i] = 0.f;
        #pragma unroll
        for (int j = 0; j < 4; j++) O[i][j] = 0.f;
    }
    const float scale = 0.125f;

    for (int jb = 0; jb <= qblk; jb++) {
        const float* Kp = g_K + ((size_t)bh * T + jb * 64) * DH;
        const float* Vp = g_V + ((size_t)bh * T + jb * 64) * DH;
        __syncthreads();
        for (int i = tid; i < 64 * 64; i += 256) {
            int s = i >> 6, d = i & 63;
            KP[d * AW + s] = Kp[i];
            Vs[s * AW + d] = Vp[i];
        }
        __syncthreads();

        float S[4][4] = {};
        #pragma unroll 8
        for (int d = 0; d < 64; d++) {
            float4 kv = *(const float4*)&KP[d * AW + tx * 4];
            #pragma unroll
            for (int i = 0; i < 4; i++) {
                float q = Qs[(ty * 4 + i) * AW + d];
                S[i][0] += q * kv.x; S[i][1] += q * kv.y;
                S[i][2] += q * kv.z; S[i][3] += q * kv.w;
            }
        }
        #pragma unroll
        for (int i = 0; i < 4; i++)
            #pragma unroll
            for (int j = 0; j < 4; j++) S[i][j] *= scale;

        if (jb == qblk) {
            #pragma unroll
            for (int i = 0; i < 4; i++)
                #pragma unroll
                for (int j = 0; j < 4; j++)
                    if (tx * 4 + j > ty * 4 + i) S[i][j] = -1e30f;
        }
        #pragma unroll
        for (int i = 0; i < 4; i++) {
            float mx = fmaxf(fmaxf(S[i][0], S[i][1]), fmaxf(S[i][2], S[i][3]));
            #pragma unroll
            for (int off = 8; off; off >>= 1)
                mx = fmaxf(mx, __shfl_xor_sync(0xffffffffu, mx, off));
            float mnew  = fmaxf(m_r[i], mx);
            float alpha = __expf(m_r[i] - mnew);
            float rs = 0.f;
            #pragma unroll
            for (int j = 0; j < 4; j++) { S[i][j] = __expf(S[i][j] - mnew); rs += S[i][j]; }
            #pragma unroll
            for (int off = 8; off; off >>= 1)
                rs += __shfl_xor_sync(0xffffffffu, rs, off);
            l_r[i] = l_r[i] * alpha + rs;
            m_r[i] = mnew;
            #pragma unroll
            for (int j = 0; j < 4; j++) O[i][j] *= alpha;
        }
        __syncthreads();
        #pragma unroll
        for (int i = 0; i < 4; i++)
            *(float4*)&KP[(ty * 4 + i) * AW + tx * 4] =
                make_float4(S[i][0], S[i][1], S[i][2], S[i][3]);
        __syncthreads();
        #pragma unroll 8
        for (int s = 0; s < 64; s++) {
            float4 v = *(const float4*)&Vs[s * AW + tx * 4];
            #pragma unroll
            for (int i = 0; i < 4; i++) {
                float p = KP[(ty * 4 + i) * AW + s];
                O[i][0] += p * v.x; O[i][1] += p * v.y;
                O[i][2] += p * v.z; O[i][3] += p * v.w;
            }
        }
    }
    const int b = bh >> 4, h = bh & 15;
    #pragma unroll
    for (int i = 0; i < 4; i++) {
        float inv = 1.0f / l_r[i];
        int t = qblk * 64 + ty * 4 + i;
        *(float4*)&g_O[((size_t)(b * T + t)) * HD + h * DH + tx * 4] =
            make_float4(O[i][0] * inv, O[i][1] * inv, O[i][2] * inv, O[i][3] * inv);
    }
}

// ---------------------------------------------------------------------------
extern "C" void kernel_launch(void* const* d_in, const int* in_sizes, int n_in,
                              void* d_out, int out_size)
{
    const float* x  = (const float*)d_in[0];
    const float* Wq = (const float*)d_in[1];
    const float* Wk = (const float*)d_in[2];
    const float* Wv = (const float*)d_in[3];
    const float* Wo = (const float*)d_in[4];
    const float* bo = (const float*)d_in[5];
    float* out = (float*)d_out;
    (void)in_sizes; (void)n_in; (void)out_size;

    cudaFuncSetAttribute(qkv_mma,     cudaFuncAttributeMaxDynamicSharedMemorySize, GEMM_SMEM);
    cudaFuncSetAttribute(outproj_mma, cudaFuncAttributeMaxDynamicSharedMemorySize, GEMM_SMEM);
    cudaFuncSetAttribute(attn_kernel, cudaFuncAttributeMaxDynamicSharedMemorySize, ATTN_SMEM);

    qkv_mma<<<dim3(M / 128, 24), 256, GEMM_SMEM>>>(x, Wq, Wk, Wv);
    attn_kernel<<<dim3(T / 64, B * H), 256, ATTN_SMEM>>>();
    outproj_mma<<<dim3(M / 128, E / 128), 256, GEMM_SMEM>>>(Wo, bo, out);
}

// round 7
// speedup vs baseline: 2.7905x; 1.4275x over previous
#include <cuda_runtime.h>
#include <cuda_bf16.h>
#include <cstdint>

// Problem constants
constexpr int B  = 4;
constexpr int T  = 1024;
constexpr int E  = 1024;
constexpr int H  = 16;
constexpr int DH = 64;
constexpr int M  = B * T;        // 4096
constexpr int HD = H * DH;       // 1024

// Scratch
__device__ float g_Q[B * H * T * DH];   // [b][h][t][d]
__device__ float g_K[B * H * T * DH];
__device__ float g_V[B * H * T * DH];
__device__ float g_O[M * HD];           // [b*T+t][h*DH+d]

// ---------------------------------------------------------------------------
// mma.sync helpers (compute_100-safe: sm_80-era PTX)
// ---------------------------------------------------------------------------
__device__ __forceinline__ uint32_t smem_u32(const void* p) {
    uint32_t a;
    asm("{ .reg .u64 t; cvta.to.shared.u64 t, %1; cvt.u32.u64 %0, t; }" : "=r"(a) : "l"(p));
    return a;
}
__device__ __forceinline__ void ldsm_x4(uint32_t& r0, uint32_t& r1, uint32_t& r2, uint32_t& r3,
                                        uint32_t addr) {
    asm volatile("ldmatrix.sync.aligned.m8n8.x4.shared.b16 {%0,%1,%2,%3}, [%4];"
                 : "=r"(r0), "=r"(r1), "=r"(r2), "=r"(r3) : "r"(addr));
}
__device__ __forceinline__ void ldsm_x2(uint32_t& r0, uint32_t& r1, uint32_t addr) {
    asm volatile("ldmatrix.sync.aligned.m8n8.x2.shared.b16 {%0,%1}, [%2];"
                 : "=r"(r0), "=r"(r1) : "r"(addr));
}
__device__ __forceinline__ void ldsm_x2_t(uint32_t& r0, uint32_t& r1, uint32_t addr) {
    asm volatile("ldmatrix.sync.aligned.m8n8.x2.trans.shared.b16 {%0,%1}, [%2];"
                 : "=r"(r0), "=r"(r1) : "r"(addr));
}
__device__ __forceinline__ void mma_bf16(float* c, const uint32_t* a, const uint32_t* b) {
    asm volatile(
        "mma.sync.aligned.m16n8k16.row.col.f32.bf16.bf16.f32 "
        "{%0,%1,%2,%3}, {%4,%5,%6,%7}, {%8,%9}, {%0,%1,%2,%3};"
        : "+f"(c[0]), "+f"(c[1]), "+f"(c[2]), "+f"(c[3])
        : "r"(a[0]), "r"(a[1]), "r"(a[2]), "r"(a[3]), "r"(b[0]), "r"(b[1]));
}

// hi/lo bf16 split of two floats -> packed u32s
__device__ __forceinline__ void split2(float a, float b, uint32_t& hi, uint32_t& lo) {
    __nv_bfloat16 ha = __float2bfloat16(a), hb = __float2bfloat16(b);
    __nv_bfloat16 la = __float2bfloat16(a - __bfloat162float(ha));
    __nv_bfloat16 lb = __float2bfloat16(b - __bfloat162float(hb));
    hi = (uint32_t)__bfloat16_as_ushort(ha) | ((uint32_t)__bfloat16_as_ushort(hb) << 16);
    lo = (uint32_t)__bfloat16_as_ushort(la) | ((uint32_t)__bfloat16_as_ushort(lb) << 16);
}

// GEMM tiling
constexpr int BK  = 32;
constexpr int NK  = 32;                   // 1024 / BK
constexpr int PK  = 40;                   // [row][k] padded k-stride (bf16)
constexpr int PKN = 136;                  // qkv B [k][n] padded n-stride (bf16)
constexpr int TA_BYTES  = 128 * PK * 2;   // 10240 per tile
constexpr int BUF_BYTES = 4 * TA_BYTES;
constexpr int GEMM_SMEM = 2 * BUF_BYTES;  // 81920

// ---------------------------------------------------------------------------
// GEMM loaders (unchanged from round-5 pass)
// ---------------------------------------------------------------------------
__device__ __forceinline__ void prefA(const float* src, int ld, int k0, float4 rA[4], int tid) {
    #pragma unroll
    for (int j = 0; j < 4; j++) {
        int flat = j * 256 + tid;
        int r = flat >> 3, kq = (flat & 7) * 4;
        rA[j] = *(const float4*)(src + (size_t)r * ld + k0 + kq);
    }
}
__device__ __forceinline__ void storeA(const float4 rA[4], char* buf, int tid) {
    __nv_bfloat16* sH = (__nv_bfloat16*)buf;
    __nv_bfloat16* sL = (__nv_bfloat16*)(buf + TA_BYTES);
    #pragma unroll
    for (int j = 0; j < 4; j++) {
        int flat = j * 256 + tid;
        int r = flat >> 3, kq = (flat & 7) * 4;
        uint32_t h01, l01, h23, l23;
        split2(rA[j].x, rA[j].y, h01, l01);
        split2(rA[j].z, rA[j].w, h23, l23);
        *(uint32_t*)(sH + r * PK + kq)     = h01;
        *(uint32_t*)(sH + r * PK + kq + 2) = h23;
        *(uint32_t*)(sL + r * PK + kq)     = l01;
        *(uint32_t*)(sL + r * PK + kq + 2) = l23;
    }
}
__device__ __forceinline__ void loadB_rows(const float* src, int ld, int k0, char* buf, int tid) {
    __nv_bfloat16* sH = (__nv_bfloat16*)(buf + 2 * TA_BYTES);
    __nv_bfloat16* sL = (__nv_bfloat16*)(buf + 3 * TA_BYTES);
    #pragma unroll
    for (int j = 0; j < 4; j++) {
        int flat = j * 256 + tid;
        int r = flat >> 3, kq = (flat & 7) * 4;
        float4 v = *(const float4*)(src + (size_t)r * ld + k0 + kq);
        uint32_t h01, l01, h23, l23;
        split2(v.x, v.y, h01, l01);
        split2(v.z, v.w, h23, l23);
        *(uint32_t*)(sH + r * PK + kq)     = h01;
        *(uint32_t*)(sH + r * PK + kq + 2) = h23;
        *(uint32_t*)(sL + r * PK + kq)     = l01;
        *(uint32_t*)(sL + r * PK + kq + 2) = l23;
    }
}
__device__ __forceinline__ void loadB_qkv(const float* Wsel, int nn0, int k0, char* buf, int tid) {
    __nv_bfloat16* sH = (__nv_bfloat16*)(buf + 2 * TA_BYTES);
    __nv_bfloat16* sL = (__nv_bfloat16*)(buf + 3 * TA_BYTES);
    #pragma unroll
    for (int j = 0; j < 2; j++) {
        int flat = j * 256 + tid;
        int k  = (flat >> 5) * 2;
        int n4 = (flat & 31) * 4;
        int ng = nn0 + n4;
        int h = ng >> 6, d = ng & 63;
        const float* base = Wsel + ((size_t)(h * E + k0 + k)) * DH + d;
        float4 v0 = *(const float4*)base;
        float4 v1 = *(const float4*)(base + DH);
        uint32_t h01, l01, h23, l23;
        split2(v0.x, v0.y, h01, l01);
        split2(v0.z, v0.w, h23, l23);
        *(uint32_t*)(sH + k * PKN + n4)     = h01;
        *(uint32_t*)(sH + k * PKN + n4 + 2) = h23;
        *(uint32_t*)(sL + k * PKN + n4)     = l01;
        *(uint32_t*)(sL + k * PKN + n4 + 2) = l23;
        split2(v1.x, v1.y, h01, l01);
        split2(v1.z, v1.w, h23, l23);
        *(uint32_t*)(sH + (k + 1) * PKN + n4)     = h01;
        *(uint32_t*)(sH + (k + 1) * PKN + n4 + 2) = h23;
        *(uint32_t*)(sL + (k + 1) * PKN + n4)     = l01;
        *(uint32_t*)(sL + (k + 1) * PKN + n4 + 2) = l23;
    }
}

template <bool BT>
__device__ __forceinline__ void gemm_compute(char* buf, float c[4][4][4],
                                             int lane, int wy, int wx) {
    const uint32_t aH = smem_u32(buf);
    const uint32_t aL = aH + TA_BYTES;
    const uint32_t bH = aH + 2 * TA_BYTES;
    const uint32_t bL = aH + 3 * TA_BYTES;
    const int arow  = wy * 64 + (lane & 15);
    const int acol8 = (lane >> 4) * 8;

    #pragma unroll
    for (int ks = 0; ks < 2; ks++) {
        const int k0 = ks * 16;
        uint32_t Bh[4][2], Bl[4][2];
        if (BT) {
            const int krow = k0 + (lane & 15);
            #pragma unroll
            for (int ni = 0; ni < 4; ni++) {
                uint32_t off = (uint32_t)(krow * PKN + wx * 32 + ni * 8) * 2;
                ldsm_x2_t(Bh[ni][0], Bh[ni][1], bH + off);
                ldsm_x2_t(Bl[ni][0], Bl[ni][1], bL + off);
            }
        } else {
            const int brow  = wx * 32 + (lane & 7);
            const int bcol8 = ((lane >> 3) & 1) * 8;
            #pragma unroll
            for (int ni = 0; ni < 4; ni++) {
                uint32_t off = (uint32_t)((brow + ni * 8) * PK + k0 + bcol8) * 2;
                ldsm_x2(Bh[ni][0], Bh[ni][1], bH + off);
                ldsm_x2(Bl[ni][0], Bl[ni][1], bL + off);
            }
        }
        #pragma unroll
        for (int mi = 0; mi < 4; mi++) {
            uint32_t Ah[4], Al[4];
            uint32_t off = (uint32_t)((arow + mi * 16) * PK + k0 + acol8) * 2;
            ldsm_x4(Ah[0], Ah[1], Ah[2], Ah[3], aH + off);
            ldsm_x4(Al[0], Al[1], Al[2], Al[3], aL + off);
            #pragma unroll
            for (int ni = 0; ni < 4; ni++) {
                mma_bf16(c[mi][ni], Ah, Bh[ni]);
                mma_bf16(c[mi][ni], Ah, Bl[ni]);
                mma_bf16(c[mi][ni], Al, Bh[ni]);
            }
        }
    }
}

// ---------------------------------------------------------------------------
// Kernel 1: QKV projection (unchanged from round-5 pass)
// ---------------------------------------------------------------------------
__global__ void __launch_bounds__(256, 2)
qkv_mma(const float* __restrict__ x,
        const float* __restrict__ Wq,
        const float* __restrict__ Wk,
        const float* __restrict__ Wv)
{
    extern __shared__ char smbuf[];
    const int tid  = threadIdx.x;
    const int lane = tid & 31;
    const int wid  = tid >> 5;
    const int wy = wid >> 2, wx = wid & 3;

    const int m0   = blockIdx.x * 128;
    const int nblk = blockIdx.y;
    const int sel  = nblk >> 3;
    const int nn0  = (nblk & 7) * 128;
    const float* Wsel = (sel == 0) ? Wq : (sel == 1) ? Wk : Wv;
    float*       Out  = (sel == 0) ? g_Q : (sel == 1) ? g_K : g_V;

    float c[4][4][4] = {};
    float4 rA[4];
    prefA(x + (size_t)m0 * E, E, 0, rA, tid);

    for (int kt = 0; kt < NK; kt++) {
        char* buf = smbuf + (kt & 1) * BUF_BYTES;
        storeA(rA, buf, tid);
        loadB_qkv(Wsel, nn0, kt * BK, buf, tid);
        __syncthreads();
        if (kt + 1 < NK) prefA(x + (size_t)m0 * E, E, (kt + 1) * BK, rA, tid);
        gemm_compute<true>(buf, c, lane, wy, wx);
    }

    const int g = lane >> 2, tg = lane & 3;
    #pragma unroll
    for (int mi = 0; mi < 4; mi++) {
        #pragma unroll
        for (int half = 0; half < 2; half++) {
            int m  = m0 + wy * 64 + mi * 16 + g + half * 8;
            int bb = m >> 10, t = m & 1023;
            #pragma unroll
            for (int ni = 0; ni < 4; ni++) {
                int n = nn0 + wx * 32 + ni * 8 + tg * 2;
                int h = n >> 6, d = n & 63;
                float2 val = make_float2(c[mi][ni][half * 2], c[mi][ni][half * 2 + 1]);
                *(float2*)(Out + ((size_t)((bb * H + h) * T + t)) * DH + d) = val;
            }
        }
    }
}

// ---------------------------------------------------------------------------
// Kernel 3: output projection (unchanged from round-5 pass)
// ---------------------------------------------------------------------------
__global__ void __launch_bounds__(256, 2)
outproj_mma(const float* __restrict__ Wo,
            const float* __restrict__ bo,
            float* __restrict__ out)
{
    extern __shared__ char smbuf[];
    const int tid  = threadIdx.x;
    const int lane = tid & 31;
    const int wid  = tid >> 5;
    const int wy = wid >> 2, wx = wid & 3;

    const int m0 = blockIdx.x * 128;
    const int n0 = blockIdx.y * 128;

    float c[4][4][4] = {};
    float4 rA[4];
    prefA(g_O + (size_t)m0 * HD, HD, 0, rA, tid);

    for (int kt = 0; kt < NK; kt++) {
        char* buf = smbuf + (kt & 1) * BUF_BYTES;
        storeA(rA, buf, tid);
        loadB_rows(Wo + (size_t)n0 * HD, HD, kt * BK, buf, tid);
        __syncthreads();
        if (kt + 1 < NK) prefA(g_O + (size_t)m0 * HD, HD, (kt + 1) * BK, rA, tid);
        gemm_compute<false>(buf, c, lane, wy, wx);
    }

    const int g = lane >> 2, tg = lane & 3;
    #pragma unroll
    for (int mi = 0; mi < 4; mi++) {
        #pragma unroll
        for (int half = 0; half < 2; half++) {
            int m = m0 + wy * 64 + mi * 16 + g + half * 8;
            #pragma unroll
            for (int ni = 0; ni < 4; ni++) {
                int n = n0 + wx * 32 + ni * 8 + tg * 2;
                float2 bv = *(const float2*)(bo + n);
                float2 val = make_float2(c[mi][ni][half * 2] + bv.x,
                                         c[mi][ni][half * 2 + 1] + bv.y);
                *(float2*)(out + (size_t)m * E + n) = val;
            }
        }
    }
}

// ---------------------------------------------------------------------------
// Kernel 2: causal flash attention on mma.sync (hi/lo split, fp32 softmax).
// CTA = 128 q-rows of one (b,h); 8 warps x 16 rows. Key tiles of 64.
// ---------------------------------------------------------------------------
constexpr int PKA = 72;                        // padded d-stride (bf16)
constexpr int QT_BYTES = 128 * PKA * 2;        // 18432
constexpr int KT_BYTES = 64 * PKA * 2;         // 9216
constexpr int ATTN_SMEM = 2 * QT_BYTES + 4 * KT_BYTES;   // 73728

__global__ void __launch_bounds__(256, 2)
attn_mma()
{
    extern __shared__ char sm[];
    __nv_bfloat16* Qh = (__nv_bfloat16*)sm;
    __nv_bfloat16* Ql = Qh + 128 * PKA;
    __nv_bfloat16* Kh = Ql + 128 * PKA;
    __nv_bfloat16* Kl = Kh + 64 * PKA;
    __nv_bfloat16* Vh = Kl + 64 * PKA;
    __nv_bfloat16* Vl = Vh + 64 * PKA;

    const int tid = threadIdx.x, lane = tid & 31, w = tid >> 5;
    const int g = lane >> 2, tg = lane & 3;
    const int qb  = 7 - blockIdx.x;            // heavy blocks first
    const int bh  = blockIdx.y;
    const int qr0 = qb * 128;
    const int rw0 = qr0 + w * 16;              // warp's first q row

    // Load Q tile once (128 x 64) -> hi/lo split
    const float* Qg = g_Q + ((size_t)bh * T + qr0) * DH;
    #pragma unroll
    for (int j = 0; j < 8; j++) {
        int idx = j * 256 + tid;
        int r = idx >> 4, c4 = (idx & 15) * 4;
        float4 v = *(const float4*)(Qg + r * DH + c4);
        uint32_t h01, l01, h23, l23;
        split2(v.x, v.y, h01, l01);
        split2(v.z, v.w, h23, l23);
        *(uint32_t*)(Qh + r * PKA + c4)     = h01;
        *(uint32_t*)(Qh + r * PKA + c4 + 2) = h23;
        *(uint32_t*)(Ql + r * PKA + c4)     = l01;
        *(uint32_t*)(Ql + r * PKA + c4 + 2) = l23;
    }

    const uint32_t aQh = smem_u32(Qh), aQl = smem_u32(Ql);
    const uint32_t aKh = smem_u32(Kh), aKl = smem_u32(Kl);
    const uint32_t aVh = smem_u32(Vh), aVl = smem_u32(Vl);

    float O[8][4] = {};
    float mrow[2] = {-1e30f, -1e30f};
    float lrow[2] = {0.f, 0.f};
    const float scale = 0.125f;

    const int jbmax = 2 * qb + 1;
    for (int jb = 0; jb <= jbmax; jb++) {
        __syncthreads();   // prior iteration's K/V reads complete
        {   // cooperative K/V tile load (64 x 64 each) -> hi/lo split
            const float* Kg = g_K + ((size_t)bh * T + jb * 64) * DH;
            const float* Vg = g_V + ((size_t)bh * T + jb * 64) * DH;
            #pragma unroll
            for (int j = 0; j < 4; j++) {
                int idx = j * 256 + tid;
                int r = idx >> 4, c4 = (idx & 15) * 4;
                float4 kv = *(const float4*)(Kg + r * DH + c4);
                float4 vv = *(const float4*)(Vg + r * DH + c4);
                uint32_t h01, l01, h23, l23;
                split2(kv.x, kv.y, h01, l01);
                split2(kv.z, kv.w, h23, l23);
                *(uint32_t*)(Kh + r * PKA + c4)     = h01;
                *(uint32_t*)(Kh + r * PKA + c4 + 2) = h23;
                *(uint32_t*)(Kl + r * PKA + c4)     = l01;
                *(uint32_t*)(Kl + r * PKA + c4 + 2) = l23;
                split2(vv.x, vv.y, h01, l01);
                split2(vv.z, vv.w, h23, l23);
                *(uint32_t*)(Vh + r * PKA + c4)     = h01;
                *(uint32_t*)(Vh + r * PKA + c4 + 2) = h23;
                *(uint32_t*)(Vl + r * PKA + c4)     = l01;
                *(uint32_t*)(Vl + r * PKA + c4 + 2) = l23;
            }
        }
        __syncthreads();

        if (jb * 64 > rw0 + 15) continue;      // tile entirely in the future for this warp

        // ---- S = Q * K^T (16 x 64), 3-term split ----
        float c[8][4] = {};
        #pragma unroll
        for (int ks = 0; ks < 4; ks++) {
            uint32_t Ah[4], Al[4];
            uint32_t offA = (uint32_t)((w * 16 + (lane & 15)) * PKA + ks * 16 + (lane >> 4) * 8) * 2;
            ldsm_x4(Ah[0], Ah[1], Ah[2], Ah[3], aQh + offA);
            ldsm_x4(Al[0], Al[1], Al[2], Al[3], aQl + offA);
            #pragma unroll
            for (int ni = 0; ni < 8; ni++) {
                uint32_t Bh[2], Bl[2];
                uint32_t offB = (uint32_t)((ni * 8 + (lane & 7)) * PKA + ks * 16 + ((lane >> 3) & 1) * 8) * 2;
                ldsm_x2(Bh[0], Bh[1], aKh + offB);
                ldsm_x2(Bl[0], Bl[1], aKl + offB);
                mma_bf16(c[ni], Ah, Bh);
                mma_bf16(c[ni], Ah, Bl);
                mma_bf16(c[ni], Al, Bh);
            }
        }

        // ---- causal mask on diagonal tiles ----
        if (jb * 64 + 63 > rw0) {
            #pragma unroll
            for (int ni = 0; ni < 8; ni++) {
                int sgb = jb * 64 + ni * 8 + tg * 2;
                #pragma unroll
                for (int e = 0; e < 4; e++) {
                    int sg = sgb + (e & 1);
                    int rg = rw0 + g + ((e >> 1) << 3);
                    if (sg > rg) c[ni][e] = -1e30f;
                }
            }
        }

        // ---- online softmax (2 rows per thread, quad-local reductions) ----
        float tm0 = -1e30f, tm1 = -1e30f;
        #pragma unroll
        for (int ni = 0; ni < 8; ni++) {
            tm0 = fmaxf(tm0, fmaxf(c[ni][0], c[ni][1]));
            tm1 = fmaxf(tm1, fmaxf(c[ni][2], c[ni][3]));
        }
        tm0 *= scale; tm1 *= scale;
        #pragma unroll
        for (int off = 1; off <= 2; off <<= 1) {
            tm0 = fmaxf(tm0, __shfl_xor_sync(0xffffffffu, tm0, off));
            tm1 = fmaxf(tm1, __shfl_xor_sync(0xffffffffu, tm1, off));
        }
        float mn0 = fmaxf(mrow[0], tm0), mn1 = fmaxf(mrow[1], tm1);
        float al0 = __expf(mrow[0] - mn0), al1 = __expf(mrow[1] - mn1);
        float rs0 = 0.f, rs1 = 0.f;
        #pragma unroll
        for (int ni = 0; ni < 8; ni++) {
            c[ni][0] = __expf(fmaf(scale, c[ni][0], -mn0));
            c[ni][1] = __expf(fmaf(scale, c[ni][1], -mn0));
            c[ni][2] = __expf(fmaf(scale, c[ni][2], -mn1));
            c[ni][3] = __expf(fmaf(scale, c[ni][3], -mn1));
            rs0 += c[ni][0] + c[ni][1];
            rs1 += c[ni][2] + c[ni][3];
        }
        #pragma unroll
        for (int off = 1; off <= 2; off <<= 1) {
            rs0 += __shfl_xor_sync(0xffffffffu, rs0, off);
            rs1 += __shfl_xor_sync(0xffffffffu, rs1, off);
        }
        lrow[0] = lrow[0] * al0 + rs0;
        lrow[1] = lrow[1] * al1 + rs1;
        mrow[0] = mn0; mrow[1] = mn1;
        #pragma unroll
        for (int ni = 0; ni < 8; ni++) {
            O[ni][0] *= al0; O[ni][1] *= al0;
            O[ni][2] *= al1; O[ni][3] *= al1;
        }

        // ---- O += P * V : P fragments built in registers from c ----
        #pragma unroll
        for (int ks = 0; ks < 4; ks++) {
            uint32_t Ph[4], Pl[4];
            split2(c[2 * ks][0],     c[2 * ks][1],     Ph[0], Pl[0]);
            split2(c[2 * ks][2],     c[2 * ks][3],     Ph[1], Pl[1]);
            split2(c[2 * ks + 1][0], c[2 * ks + 1][1], Ph[2], Pl[2]);
            split2(c[2 * ks + 1][2], c[2 * ks + 1][3], Ph[3], Pl[3]);
            #pragma unroll
            for (int ni = 0; ni < 8; ni++) {
                uint32_t Bh[2], Bl[2];
                uint32_t offV = (uint32_t)((ks * 16 + (lane & 15)) * PKA + ni * 8) * 2;
                ldsm_x2_t(Bh[0], Bh[1], aVh + offV);
                ldsm_x2_t(Bl[0], Bl[1], aVl + offV);
                mma_bf16(O[ni], Ph, Bh);
                mma_bf16(O[ni], Ph, Bl);
                mma_bf16(O[ni], Pl, Bh);
            }
        }
    }

    // ---- epilogue: normalize, write [b*T+t][h*DH+d] ----
    const float inv0 = 1.0f / lrow[0], inv1 = 1.0f / lrow[1];
    const int b = bh >> 4, h = bh & 15;
    const int t0 = rw0 + g, t1 = t0 + 8;
    #pragma unroll
    for (int ni = 0; ni < 8; ni++) {
        int col = h * DH + ni * 8 + tg * 2;
        *(float2*)(g_O + (size_t)(b * T + t0) * HD + col) =
            make_float2(O[ni][0] * inv0, O[ni][1] * inv0);
        *(float2*)(g_O + (size_t)(b * T + t1) * HD + col) =
            make_float2(O[ni][2] * inv1, O[ni][3] * inv1);
    }
}

// ---------------------------------------------------------------------------
extern "C" void kernel_launch(void* const* d_in, const int* in_sizes, int n_in,
                              void* d_out, int out_size)
{
    const float* x  = (const float*)d_in[0];
    const float* Wq = (const float*)d_in[1];
    const float* Wk = (const float*)d_in[2];
    const float* Wv = (const float*)d_in[3];
    const float* Wo = (const float*)d_in[4];
    const float* bo = (const float*)d_in[5];
    float* out = (float*)d_out;
    (void)in_sizes; (void)n_in; (void)out_size;

    cudaFuncSetAttribute(qkv_mma,     cudaFuncAttributeMaxDynamicSharedMemorySize, GEMM_SMEM);
    cudaFuncSetAttribute(outproj_mma, cudaFuncAttributeMaxDynamicSharedMemorySize, GEMM_SMEM);
    cudaFuncSetAttribute(attn_mma,    cudaFuncAttributeMaxDynamicSharedMemorySize, ATTN_SMEM);

    qkv_mma<<<dim3(M / 128, 24), 256, GEMM_SMEM>>>(x, Wq, Wk, Wv);
    attn_mma<<<dim3(T / 128, B * H), 256, ATTN_SMEM>>>();
    outproj_mma<<<dim3(M / 128, E / 128), 256, GEMM_SMEM>>>(Wo, bo, out);
}